// round 16
// baseline (speedup 1.0000x reference)
#include <cuda_runtime.h>
#include <cstdint>

#define HIDDEN 1024
#define HEADS 16
#define HDIM 64
#define BATCH 2
#define SEQ 2048
#define MROWS (BATCH * SEQ)   // 4096

// ---------------- scratch (device globals; allocation-free) ----------------
__device__ float g_Q[(size_t)BATCH * HEADS * SEQ * HDIM];   // raw fp32
__device__ float g_K[(size_t)BATCH * HEADS * SEQ * HDIM];   // tf32-rounded
__device__ float g_V[(size_t)BATCH * HEADS * SEQ * HDIM];   // tf32-rounded
__device__ float g_att[(size_t)BATCH * SEQ * HIDDEN];       // tf32-rounded
// tf32-pre-rounded copies of the external inputs
__device__ float g_xr[(size_t)MROWS * HIDDEN];
__device__ float g_qkvwr[(size_t)3 * HIDDEN * HIDDEN];
__device__ float g_owr[(size_t)HIDDEN * HIDDEN];

// ---------------- helpers ---------------------------------------------------
__device__ __forceinline__ float tf32_rna(float x) {
    uint32_t u;
    asm("cvt.rna.tf32.f32 %0, %1;" : "=r"(u) : "f"(x));
    return __uint_as_float(u);
}
__device__ __forceinline__ float ex2(float x) {
    float r;
    asm("ex2.approx.ftz.f32 %0, %1;" : "=f"(r) : "f"(x));
    return r;
}

// D += A(16x8 tf32) * B(8x8 tf32), fp32 accumulate
__device__ __forceinline__ void mma8(float* d, const uint32_t* a, const uint32_t* b) {
    asm volatile(
        "mma.sync.aligned.m16n8k8.row.col.f32.tf32.tf32.f32 "
        "{%0,%1,%2,%3}, {%4,%5,%6,%7}, {%8,%9}, {%0,%1,%2,%3};\n"
        : "+f"(d[0]), "+f"(d[1]), "+f"(d[2]), "+f"(d[3])
        : "r"(a[0]), "r"(a[1]), "r"(a[2]), "r"(a[3]), "r"(b[0]), "r"(b[1]));
}

__device__ __forceinline__ void cp16(uint32_t smem_dst, const float* gmem_src) {
    asm volatile("cp.async.ca.shared.global [%0], [%1], 16;\n"
                 :: "r"(smem_dst), "l"(gmem_src));
}
__device__ __forceinline__ void cp_commit() {
    asm volatile("cp.async.commit_group;\n" ::: "memory");
}
__device__ __forceinline__ void cp_wait0() {
    asm volatile("cp.async.wait_group 0;\n" ::: "memory");
}

// ---------------- pre-round inputs to tf32 ----------------------------------
__global__ void round_pre(const float* __restrict__ x,
                          const float* __restrict__ w1,
                          const float* __restrict__ w2)
{
    const size_t NX  = (size_t)MROWS * HIDDEN / 4;       // float4 counts
    const size_t NW1 = (size_t)3 * HIDDEN * HIDDEN / 4;
    const size_t NW2 = (size_t)HIDDEN * HIDDEN / 4;
    size_t i0 = (size_t)blockIdx.x * blockDim.x + threadIdx.x;
    size_t st = (size_t)gridDim.x * blockDim.x;
    float4* dx = (float4*)g_xr;
    float4* d1 = (float4*)g_qkvwr;
    float4* d2 = (float4*)g_owr;
    for (size_t j = i0; j < NX; j += st) {
        float4 v = ((const float4*)x)[j];
        dx[j] = make_float4(tf32_rna(v.x), tf32_rna(v.y), tf32_rna(v.z), tf32_rna(v.w));
    }
    for (size_t j = i0; j < NW1; j += st) {
        float4 v = ((const float4*)w1)[j];
        d1[j] = make_float4(tf32_rna(v.x), tf32_rna(v.y), tf32_rna(v.z), tf32_rna(v.w));
    }
    for (size_t j = i0; j < NW2; j += st) {
        float4 v = ((const float4*)w2)[j];
        d2[j] = make_float4(tf32_rna(v.x), tf32_rna(v.y), tf32_rna(v.z), tf32_rna(v.w));
    }
}

// ---------------- 1xTF32 GEMM:  C[m,n] = sum_k A[m,k]*B[n,k] + bias[n] ------
// Inputs already tf32-rounded. cp.async double-buffered staging, no STS.
// MODE 1: A = g_xr,  B = g_qkvwr, epilogue scatters Q (raw) / K,V (tf32-rna)
// MODE 2: A = g_att, B = g_owr,   epilogue writes plain row-major C
// CTA tile 128x128, BK=32, 256 threads = 8 warps (4m x 2n), warp tile 32x64.
#define GPAD 36
#define GBUF (2 * 128 * GPAD)                       // floats per buffer (A+B)
#define GEMM_SMEM (2 * GBUF * (int)sizeof(float))   // 73728 bytes

template <int MODE>
__global__ __launch_bounds__(256, 2) void gemm_tf32(
    const float* __restrict__ bias, float* __restrict__ C,
    int N, int K)
{
    extern __shared__ float sm[];

    const int tid  = threadIdx.x;
    const int lane = tid & 31, warp = tid >> 5;
    const int g = lane >> 2, tig = lane & 3;
    const int wm = (warp >> 1) * 32;    // warp row base
    const int wn = (warp & 1) * 64;     // warp col base

    const float* Ab = (MODE == 2 ? g_att : g_xr) + (size_t)blockIdx.y * 128 * K;
    const float* Bb = (MODE == 2 ? g_owr : g_qkvwr) + (size_t)blockIdx.x * 128 * K;

    const int r0 = tid >> 3;            // 0..31 -> rows r0, r0+32, r0+64, r0+96
    const int c0 = (tid & 7) << 2;      // 0,4,..28

    const uint32_t sbase = (uint32_t)__cvta_generic_to_shared(sm);

    float acc[2][8][4];
#pragma unroll
    for (int mt = 0; mt < 2; mt++)
#pragma unroll
        for (int nt = 0; nt < 8; nt++)
#pragma unroll
            for (int j = 0; j < 4; j++) acc[mt][nt][j] = 0.0f;

    // stage buffer 0 (async)
#pragma unroll
    for (int i = 0; i < 4; i++) {
        int row = r0 + i * 32;
        cp16(sbase + (uint32_t)(row * GPAD + c0) * 4, Ab + (size_t)row * K + c0);
        cp16(sbase + (uint32_t)(128 * GPAD + row * GPAD + c0) * 4, Bb + (size_t)row * K + c0);
    }
    cp_commit();

    const int NT = K / 32;
    for (int it = 0; it < NT; it++) {
        cp_wait0();        // this thread's stage of buf[it&1] landed
        __syncthreads();   // all threads' stages visible; all done reading buf[(it+1)&1]

        if (it + 1 < NT) {   // issue next tile async; lands under the MMA below
            int k0 = (it + 1) * 32;
            uint32_t bo = (uint32_t)(((it + 1) & 1) * GBUF);
#pragma unroll
            for (int i = 0; i < 4; i++) {
                int row = r0 + i * 32;
                cp16(sbase + (bo + row * GPAD + c0) * 4, Ab + (size_t)row * K + k0 + c0);
                cp16(sbase + (bo + 128 * GPAD + row * GPAD + c0) * 4,
                     Bb + (size_t)row * K + k0 + c0);
            }
            cp_commit();
        }

        const uint32_t* uA = (const uint32_t*)(sm + (it & 1) * GBUF);
        const uint32_t* uB = uA + 128 * GPAD;

#pragma unroll
        for (int ks = 0; ks < 4; ks++) {
            const int k0 = ks * 8;
            uint32_t ah[2][4];
#pragma unroll
            for (int mt = 0; mt < 2; mt++) {
                int base = (wm + mt * 16 + g) * GPAD + k0 + tig;
                ah[mt][0] = uA[base];
                ah[mt][1] = uA[base + 8 * GPAD];
                ah[mt][2] = uA[base + 4];
                ah[mt][3] = uA[base + 8 * GPAD + 4];
            }
#pragma unroll
            for (int nt = 0; nt < 8; nt++) {
                int base = (wn + nt * 8 + g) * GPAD + k0 + tig;
                uint32_t bh[2] = {uB[base], uB[base + 4]};
                mma8(acc[0][nt], ah[0], bh);
                mma8(acc[1][nt], ah[1], bh);
            }
        }
    }

    // epilogue
#pragma unroll
    for (int mt = 0; mt < 2; mt++) {
#pragma unroll
        for (int half = 0; half < 2; half++) {
            int m = blockIdx.y * 128 + wm + mt * 16 + g + half * 8;
#pragma unroll
            for (int nt = 0; nt < 8; nt++) {
                int n = blockIdx.x * 128 + wn + nt * 8 + 2 * tig;
                float v0 = acc[mt][nt][half * 2 + 0] + bias[n];
                float v1 = acc[mt][nt][half * 2 + 1] + bias[n + 1];
                if (MODE == 1) {
                    int b = m >> 11;            // SEQ = 2048
                    int s = m & (SEQ - 1);
                    int h = n / 192;
                    int jj = n - h * 192;
                    float* dst;
                    if (jj < 64) {
                        dst = g_Q;               // raw; attn scales+rounds
                    } else {
                        dst = (jj < 128) ? g_K : g_V;
                        v0 = tf32_rna(v0);       // pre-round so attn can cp.async
                        v1 = tf32_rna(v1);
                    }
                    size_t idx = ((((size_t)b * HEADS + h) * SEQ + s) << 6) + (jj & 63);
                    *(float2*)(dst + idx) = make_float2(v0, v1);
                } else {
                    *(float2*)(C + (size_t)m * N + n) = make_float2(v0, v1);
                }
            }
        }
    }
}

// ---------------- flash attention, TF32 mma (online softmax) ----------------
// One CTA per (b, h, 128-row q-block). 128 thr = 4 warps; warp owns 32 q-rows
// (mt=2). 32-key K/V blocks, cp.async double-buffered. Small smem (86 KB) ->
// 2 CTAs/SM so softmax of one CTA overlaps MMAs of the other.
#define QROWS 128
#define KBLK 32
#define APAD 68
#define PPAD 36
#define AKV (KBLK * APAD)                    // floats per K or V buffer
#define OFF_K (QROWS * APAD)                 // Qs then K buffers
#define OFF_V (OFF_K + 2 * AKV)
#define OFF_P (OFF_V + 2 * AKV)
#define ATTN_SMEM ((OFF_P + QROWS * PPAD) * (int)sizeof(float))   // 88064
#define QSC 0.18033688011112042f   // 0.125 * log2(e)

__global__ __launch_bounds__(128, 2) void attn_tf32()
{
    extern __shared__ float sm[];
    float* Qs = sm;                          // [128][APAD] (tf32, pre-scaled)
    float* Ks = sm + OFF_K;                  // 2 x [32][APAD] key-major
    float* Vs = sm + OFF_V;                  // 2 x [32][APAD] key-major
    float* Ps = sm + OFF_P;                  // [128][PPAD] row-major P
    const uint32_t* uQ = (const uint32_t*)Qs;
    const uint32_t* uP = (const uint32_t*)Ps;
    const uint32_t sbase = (uint32_t)__cvta_generic_to_shared(sm);
    const uint32_t sK0 = sbase + OFF_K * 4;
    const uint32_t sV0 = sbase + OFF_V * 4;

    const int tid  = threadIdx.x;
    const int lane = tid & 31, warp = tid >> 5;   // 0..3
    const int g = lane >> 2, tig = lane & 3;
    const int wq = warp * 32;                // warp's query-row base (0..96)

    const int qb = blockIdx.x, h = blockIdx.y, b = blockIdx.z;
    const size_t headBase = ((size_t)b * HEADS + h) * SEQ * HDIM;
    const float* Qg = g_Q + headBase + (size_t)qb * QROWS * HDIM;
    const float* Kg = g_K + headBase;
    const float* Vg = g_V + headBase;

    // stage K/V block 0 via cp.async (data already tf32-rounded)
    // 32 rows x 64 cols = 512 float4 slots; 128 thr x 4
#pragma unroll
    for (int t = 0; t < 4; t++) {
        int slot = tid + t * 128;
        int row = slot >> 4, c = (slot & 15) << 2;
        cp16(sK0 + (uint32_t)(row * APAD + c) * 4, Kg + (size_t)row * HDIM + c);
        cp16(sV0 + (uint32_t)(row * APAD + c) * 4, Vg + (size_t)row * HDIM + c);
    }
    cp_commit();

    // stage Q once: scale by 0.125*log2e, round to tf32
    {
        int r = tid >> 4, c = (tid & 15) << 2;   // r 0..7, c 0..60
#pragma unroll
        for (int i = 0; i < 16; i++) {
            int row = r + i * 8;
            float4 v = *(const float4*)(Qg + (size_t)row * HDIM + c);
            *(float4*)(Qs + row * APAD + c) =
                make_float4(tf32_rna(v.x * QSC), tf32_rna(v.y * QSC),
                            tf32_rna(v.z * QSC), tf32_rna(v.w * QSC));
        }
    }

    float m_i[2][2], l_i[2][2];
    float o[2][8][4];
#pragma unroll
    for (int mt = 0; mt < 2; mt++) {
#pragma unroll
        for (int half = 0; half < 2; half++) { m_i[mt][half] = -3.0e38f; l_i[mt][half] = 0.0f; }
#pragma unroll
        for (int nt = 0; nt < 8; nt++)
#pragma unroll
            for (int j = 0; j < 4; j++) o[mt][nt][j] = 0.0f;
    }

    const int NB = SEQ / KBLK;               // 64
    for (int kb = 0; kb < NB; kb++) {
        cp_wait0();
        __syncthreads();   // buf[kb&1] staged; reads of buf[(kb+1)&1] (iter kb-1) done
        const uint32_t* uK = (const uint32_t*)(Ks + (kb & 1) * AKV);
        const uint32_t* uV = (const uint32_t*)(Vs + (kb & 1) * AKV);

        if (kb + 1 < NB) {   // issue next K/V block async into the other buffer
            const float* Kn = Kg + (size_t)(kb + 1) * KBLK * HDIM;
            const float* Vn = Vg + (size_t)(kb + 1) * KBLK * HDIM;
            uint32_t bo = (uint32_t)(((kb + 1) & 1) * AKV) * 4;
#pragma unroll
            for (int t = 0; t < 4; t++) {
                int slot = tid + t * 128;
                int row = slot >> 4, c = (slot & 15) << 2;
                cp16(sK0 + bo + (uint32_t)(row * APAD + c) * 4, Kn + (size_t)row * HDIM + c);
                cp16(sV0 + bo + (uint32_t)(row * APAD + c) * 4, Vn + (size_t)row * HDIM + c);
            }
            cp_commit();
        }

        // ---- S = Q K^T (32 rows x 32 keys per warp, log2-scaled) ----
        float s[2][4][4];
#pragma unroll
        for (int mt = 0; mt < 2; mt++)
#pragma unroll
            for (int nt = 0; nt < 4; nt++)
#pragma unroll
                for (int j = 0; j < 4; j++) s[mt][nt][j] = 0.0f;

#pragma unroll
        for (int ks = 0; ks < 8; ks++) {
            const int k0 = ks * 8;
            uint32_t qa[2][4];
#pragma unroll
            for (int mt = 0; mt < 2; mt++) {
                int base = (wq + mt * 16 + g) * APAD + k0 + tig;
                qa[mt][0] = uQ[base];
                qa[mt][1] = uQ[base + 8 * APAD];
                qa[mt][2] = uQ[base + 4];
                qa[mt][3] = uQ[base + 8 * APAD + 4];
            }
#pragma unroll
            for (int nt = 0; nt < 4; nt++) {
                int bb = (nt * 8 + g) * APAD + k0 + tig;
                uint32_t kf[2] = {uK[bb], uK[bb + 4]};
                mma8(s[0][nt], qa[0], kf);
                mma8(s[1][nt], qa[1], kf);
            }
        }

        // ---- online softmax (log2 domain) ----
#pragma unroll
        for (int mt = 0; mt < 2; mt++) {
#pragma unroll
            for (int half = 0; half < 2; half++) {
                float rmax = -3.0e38f;
#pragma unroll
                for (int nt = 0; nt < 4; nt++)
                    rmax = fmaxf(rmax, fmaxf(s[mt][nt][half * 2], s[mt][nt][half * 2 + 1]));
                rmax = fmaxf(rmax, __shfl_xor_sync(0xffffffffu, rmax, 1));
                rmax = fmaxf(rmax, __shfl_xor_sync(0xffffffffu, rmax, 2));
                float mnew  = fmaxf(m_i[mt][half], rmax);
                float alpha = ex2(m_i[mt][half] - mnew);
                m_i[mt][half] = mnew;
                float rs = 0.0f;
                int prow = (wq + mt * 16 + g + half * 8) * PPAD + 2 * tig;
#pragma unroll
                for (int nt = 0; nt < 4; nt++) {
                    float p0 = ex2(s[mt][nt][half * 2] - mnew);
                    float p1 = ex2(s[mt][nt][half * 2 + 1] - mnew);
                    rs += p0 + p1;
                    *(float2*)(Ps + prow + nt * 8) = make_float2(tf32_rna(p0), tf32_rna(p1));
                }
                rs += __shfl_xor_sync(0xffffffffu, rs, 1);
                rs += __shfl_xor_sync(0xffffffffu, rs, 2);
                l_i[mt][half] = l_i[mt][half] * alpha + rs;
#pragma unroll
                for (int nt = 0; nt < 8; nt++) {
                    o[mt][nt][half * 2]     *= alpha;
                    o[mt][nt][half * 2 + 1] *= alpha;
                }
            }
        }
        __syncwarp();   // Ps rows are warp-private; make stores visible

        // ---- O += P V  (k-dim = 32 keys -> 4 k-steps) ----
#pragma unroll
        for (int ks = 0; ks < 4; ks++) {
            const int k0 = ks * 8;
            uint32_t pa[2][4];
#pragma unroll
            for (int mt = 0; mt < 2; mt++) {
                int base = (wq + mt * 16 + g) * PPAD + k0 + tig;
                pa[mt][0] = uP[base];
                pa[mt][1] = uP[base + 8 * PPAD];
                pa[mt][2] = uP[base + 4];
                pa[mt][3] = uP[base + 8 * PPAD + 4];
            }
#pragma unroll
            for (int nt = 0; nt < 8; nt++) {
                uint32_t vf[2] = {uV[(k0 + tig) * APAD + nt * 8 + g],
                                  uV[(k0 + tig + 4) * APAD + nt * 8 + g]};
                mma8(o[0][nt], pa[0], vf);
                mma8(o[1][nt], pa[1], vf);
            }
        }
    }

    // ---- epilogue: normalize, round to tf32 (gemm2 reads raw), write -------
    float* ob = g_att + ((size_t)b * SEQ + (size_t)qb * QROWS) * HIDDEN + h * HDIM;
#pragma unroll
    for (int mt = 0; mt < 2; mt++) {
#pragma unroll
        for (int half = 0; half < 2; half++) {
            float inv = 1.0f / l_i[mt][half];
            int row = wq + mt * 16 + g + half * 8;
#pragma unroll
            for (int nt = 0; nt < 8; nt++)
                *(float2*)(ob + (size_t)row * HIDDEN + nt * 8 + 2 * tig) =
                    make_float2(tf32_rna(o[mt][nt][half * 2] * inv),
                                tf32_rna(o[mt][nt][half * 2 + 1] * inv));
        }
    }
}

// ---------------- launch ---------------------------------------------------
extern "C" void kernel_launch(void* const* d_in, const int* in_sizes, int n_in,
                              void* d_out, int out_size)
{
    const float* x     = (const float*)d_in[0];
    const float* qkv_w = (const float*)d_in[1];
    const float* qkv_b = (const float*)d_in[2];
    const float* o_w   = (const float*)d_in[3];
    const float* o_b   = (const float*)d_in[4];
    float* out = (float*)d_out;

    cudaFuncSetAttribute(gemm_tf32<1>, cudaFuncAttributeMaxDynamicSharedMemorySize, GEMM_SMEM);
    cudaFuncSetAttribute(gemm_tf32<2>, cudaFuncAttributeMaxDynamicSharedMemorySize, GEMM_SMEM);
    cudaFuncSetAttribute(attn_tf32,   cudaFuncAttributeMaxDynamicSharedMemorySize, ATTN_SMEM);

    // 0) round inputs to tf32 once
    round_pre<<<592, 256>>>(x, qkv_w, o_w);
    // 1) QKV projection (1xTF32, cp.async) + scatter; K/V pre-rounded
    gemm_tf32<1><<<dim3(3 * HIDDEN / 128, MROWS / 128), dim3(256), GEMM_SMEM>>>(
        qkv_b, nullptr, 3 * HIDDEN, HIDDEN);
    // 2) attention (1xTF32, 128-row q-blocks, 2 CTAs/SM)
    attn_tf32<<<dim3(SEQ / QROWS, HEADS, BATCH), dim3(128), ATTN_SMEM>>>();
    // 3) output projection (1xTF32, cp.async)
    gemm_tf32<2><<<dim3(HIDDEN / 128, MROWS / 128), dim3(256), GEMM_SMEM>>>(
        o_b, out, HIDDEN, HIDDEN);
}

// round 17
// speedup vs baseline: 1.0529x; 1.0529x over previous
#include <cuda_runtime.h>
#include <cstdint>

#define HIDDEN 1024
#define HEADS 16
#define HDIM 64
#define BATCH 2
#define SEQ 2048
#define MROWS (BATCH * SEQ)   // 4096

// ---------------- scratch (device globals; allocation-free) ----------------
__device__ float g_Q[(size_t)BATCH * HEADS * SEQ * HDIM];   // raw fp32
__device__ float g_K[(size_t)BATCH * HEADS * SEQ * HDIM];   // tf32-rounded
__device__ float g_V[(size_t)BATCH * HEADS * SEQ * HDIM];   // tf32-rounded
__device__ float g_att[(size_t)BATCH * SEQ * HIDDEN];       // tf32-rounded
// tf32-pre-rounded copies of the external inputs
__device__ float g_xr[(size_t)MROWS * HIDDEN];
__device__ float g_qkvwr[(size_t)3 * HIDDEN * HIDDEN];
__device__ float g_owr[(size_t)HIDDEN * HIDDEN];

// ---------------- helpers ---------------------------------------------------
__device__ __forceinline__ float tf32_rna(float x) {
    uint32_t u;
    asm("cvt.rna.tf32.f32 %0, %1;" : "=r"(u) : "f"(x));
    return __uint_as_float(u);
}
__device__ __forceinline__ float ex2(float x) {
    float r;
    asm("ex2.approx.ftz.f32 %0, %1;" : "=f"(r) : "f"(x));
    return r;
}

// D += A(16x8 tf32) * B(8x8 tf32), fp32 accumulate
__device__ __forceinline__ void mma8(float* d, const uint32_t* a, const uint32_t* b) {
    asm volatile(
        "mma.sync.aligned.m16n8k8.row.col.f32.tf32.tf32.f32 "
        "{%0,%1,%2,%3}, {%4,%5,%6,%7}, {%8,%9}, {%0,%1,%2,%3};\n"
        : "+f"(d[0]), "+f"(d[1]), "+f"(d[2]), "+f"(d[3])
        : "r"(a[0]), "r"(a[1]), "r"(a[2]), "r"(a[3]), "r"(b[0]), "r"(b[1]));
}

__device__ __forceinline__ void cp16(uint32_t smem_dst, const float* gmem_src) {
    asm volatile("cp.async.ca.shared.global [%0], [%1], 16;\n"
                 :: "r"(smem_dst), "l"(gmem_src));
}
__device__ __forceinline__ void cp_commit() {
    asm volatile("cp.async.commit_group;\n" ::: "memory");
}
__device__ __forceinline__ void cp_wait0() {
    asm volatile("cp.async.wait_group 0;\n" ::: "memory");
}

// ---------------- pre-round inputs to tf32 ----------------------------------
__global__ void round_pre(const float* __restrict__ x,
                          const float* __restrict__ w1,
                          const float* __restrict__ w2)
{
    const size_t NX  = (size_t)MROWS * HIDDEN / 4;       // float4 counts
    const size_t NW1 = (size_t)3 * HIDDEN * HIDDEN / 4;
    const size_t NW2 = (size_t)HIDDEN * HIDDEN / 4;
    size_t i0 = (size_t)blockIdx.x * blockDim.x + threadIdx.x;
    size_t st = (size_t)gridDim.x * blockDim.x;
    float4* dx = (float4*)g_xr;
    float4* d1 = (float4*)g_qkvwr;
    float4* d2 = (float4*)g_owr;
    for (size_t j = i0; j < NX; j += st) {
        float4 v = ((const float4*)x)[j];
        dx[j] = make_float4(tf32_rna(v.x), tf32_rna(v.y), tf32_rna(v.z), tf32_rna(v.w));
    }
    for (size_t j = i0; j < NW1; j += st) {
        float4 v = ((const float4*)w1)[j];
        d1[j] = make_float4(tf32_rna(v.x), tf32_rna(v.y), tf32_rna(v.z), tf32_rna(v.w));
    }
    for (size_t j = i0; j < NW2; j += st) {
        float4 v = ((const float4*)w2)[j];
        d2[j] = make_float4(tf32_rna(v.x), tf32_rna(v.y), tf32_rna(v.z), tf32_rna(v.w));
    }
}

// ---------------- 1xTF32 GEMM:  C[m,n] = sum_k A[m,k]*B[n,k] + bias[n] ------
// Inputs already tf32-rounded. cp.async double-buffered staging, no STS.
// MODE 1: A = g_xr,  B = g_qkvwr, epilogue scatters Q (raw) / K,V (tf32-rna)
// MODE 2: A = g_att, B = g_owr,   epilogue writes plain row-major C
// CTA tile 128x128, BK=32, 128 threads = 4 warps (2m x 2n), warp tile 64x64.
// 1.0 LDS per MMA; 2 CTAs/SM.
#define GPAD 36
#define GBUF (2 * 128 * GPAD)                       // floats per buffer (A+B)
#define GEMM_SMEM (2 * GBUF * (int)sizeof(float))   // 73728 bytes

template <int MODE>
__global__ __launch_bounds__(128, 2) void gemm_tf32(
    const float* __restrict__ bias, float* __restrict__ C,
    int N, int K)
{
    extern __shared__ float sm[];

    const int tid  = threadIdx.x;
    const int lane = tid & 31, warp = tid >> 5;   // 0..3
    const int g = lane >> 2, tig = lane & 3;
    const int wm = (warp >> 1) * 64;    // warp row base (0,64)
    const int wn = (warp & 1) * 64;     // warp col base (0,64)

    const float* Ab = (MODE == 2 ? g_att : g_xr) + (size_t)blockIdx.y * 128 * K;
    const float* Bb = (MODE == 2 ? g_owr : g_qkvwr) + (size_t)blockIdx.x * 128 * K;

    const int r0 = tid >> 3;            // 0..15 -> rows r0 + i*16
    const int c0 = (tid & 7) << 2;      // 0,4,..28

    const uint32_t sbase = (uint32_t)__cvta_generic_to_shared(sm);

    float acc[4][8][4];                 // 128 registers of accumulator
#pragma unroll
    for (int mt = 0; mt < 4; mt++)
#pragma unroll
        for (int nt = 0; nt < 8; nt++)
#pragma unroll
            for (int j = 0; j < 4; j++) acc[mt][nt][j] = 0.0f;

    // stage buffer 0 (async): 8 rows of A + 8 rows of B per thread
#pragma unroll
    for (int i = 0; i < 8; i++) {
        int row = r0 + i * 16;
        cp16(sbase + (uint32_t)(row * GPAD + c0) * 4, Ab + (size_t)row * K + c0);
        cp16(sbase + (uint32_t)(128 * GPAD + row * GPAD + c0) * 4, Bb + (size_t)row * K + c0);
    }
    cp_commit();

    const int NT = K / 32;
    for (int it = 0; it < NT; it++) {
        cp_wait0();        // this thread's stage of buf[it&1] landed
        __syncthreads();   // all threads' stages visible; all done reading buf[(it+1)&1]

        if (it + 1 < NT) {   // issue next tile async; lands under the MMA below
            int k0 = (it + 1) * 32;
            uint32_t bo = (uint32_t)(((it + 1) & 1) * GBUF);
#pragma unroll
            for (int i = 0; i < 8; i++) {
                int row = r0 + i * 16;
                cp16(sbase + (bo + row * GPAD + c0) * 4, Ab + (size_t)row * K + k0 + c0);
                cp16(sbase + (bo + 128 * GPAD + row * GPAD + c0) * 4,
                     Bb + (size_t)row * K + k0 + c0);
            }
            cp_commit();
        }

        const uint32_t* uA = (const uint32_t*)(sm + (it & 1) * GBUF);
        const uint32_t* uB = uA + 128 * GPAD;

#pragma unroll
        for (int ks = 0; ks < 4; ks++) {
            const int k0 = ks * 8;
            uint32_t ah[4][4];
#pragma unroll
            for (int mt = 0; mt < 4; mt++) {
                int base = (wm + mt * 16 + g) * GPAD + k0 + tig;
                ah[mt][0] = uA[base];
                ah[mt][1] = uA[base + 8 * GPAD];
                ah[mt][2] = uA[base + 4];
                ah[mt][3] = uA[base + 8 * GPAD + 4];
            }
#pragma unroll
            for (int nt = 0; nt < 8; nt++) {
                int base = (wn + nt * 8 + g) * GPAD + k0 + tig;
                uint32_t bh[2] = {uB[base], uB[base + 4]};
#pragma unroll
                for (int mt = 0; mt < 4; mt++)
                    mma8(acc[mt][nt], ah[mt], bh);
            }
        }
    }

    // epilogue
#pragma unroll
    for (int mt = 0; mt < 4; mt++) {
#pragma unroll
        for (int half = 0; half < 2; half++) {
            int m = blockIdx.y * 128 + wm + mt * 16 + g + half * 8;
#pragma unroll
            for (int nt = 0; nt < 8; nt++) {
                int n = blockIdx.x * 128 + wn + nt * 8 + 2 * tig;
                float v0 = acc[mt][nt][half * 2 + 0] + bias[n];
                float v1 = acc[mt][nt][half * 2 + 1] + bias[n + 1];
                if (MODE == 1) {
                    int b = m >> 11;            // SEQ = 2048
                    int s = m & (SEQ - 1);
                    int h = n / 192;
                    int jj = n - h * 192;
                    float* dst;
                    if (jj < 64) {
                        dst = g_Q;               // raw; attn scales+rounds
                    } else {
                        dst = (jj < 128) ? g_K : g_V;
                        v0 = tf32_rna(v0);       // pre-round so attn can cp.async
                        v1 = tf32_rna(v1);
                    }
                    size_t idx = ((((size_t)b * HEADS + h) * SEQ + s) << 6) + (jj & 63);
                    *(float2*)(dst + idx) = make_float2(v0, v1);
                } else {
                    *(float2*)(C + (size_t)m * N + n) = make_float2(v0, v1);
                }
            }
        }
    }
}

// ---------------- flash attention, TF32 mma (online softmax) ----------------
// (R14 config) One CTA per (b, h, 256-row q-block). 256 thr = 8 warps; warp
// owns 32 q-rows (mt=2). 64-key blocks, cp.async double-buffered K/V,
// log2-domain softmax.
#define APAD 68
#define AKV (64 * APAD)
#define ATTN_SMEM ((256 + 2 * 64 + 2 * 64 + 256) * APAD * (int)sizeof(float)) // 208896
#define QSC 0.18033688011112042f   // 0.125 * log2(e)

__global__ __launch_bounds__(256, 1) void attn_tf32()
{
    extern __shared__ float sm[];
    float* Qs = sm;                         // [256][APAD]  (tf32, pre-scaled)
    float* Ks = sm + 256 * APAD;            // 2 x [64][APAD] key-major
    float* Vs = Ks + 2 * AKV;               // 2 x [64][APAD] key-major
    float* Ps = Vs + 2 * AKV;               // [256][APAD]  row-major P
    const uint32_t* uQ = (const uint32_t*)Qs;
    const uint32_t* uP = (const uint32_t*)Ps;
    const uint32_t sbase = (uint32_t)__cvta_generic_to_shared(sm);
    const uint32_t sK0 = sbase + 256 * APAD * 4;
    const uint32_t sV0 = sK0 + 2 * AKV * 4;

    const int tid  = threadIdx.x;
    const int lane = tid & 31, warp = tid >> 5;   // 0..7
    const int g = lane >> 2, tig = lane & 3;
    const int wq = warp * 32;               // warp's query-row base (0..224)

    const int qb = blockIdx.x, h = blockIdx.y, b = blockIdx.z;
    const size_t headBase = ((size_t)b * HEADS + h) * SEQ * HDIM;
    const float* Qg = g_Q + headBase + (size_t)qb * 256 * HDIM;
    const float* Kg = g_K + headBase;
    const float* Vg = g_V + headBase;

    // stage K/V block 0 via cp.async (data already tf32-rounded)
#pragma unroll
    for (int t = 0; t < 4; t++) {
        int slot = tid + t * 256;            // 0..1023
        int row = slot >> 4, c = (slot & 15) << 2;
        cp16(sK0 + (uint32_t)(row * APAD + c) * 4, Kg + (size_t)row * HDIM + c);
        cp16(sV0 + (uint32_t)(row * APAD + c) * 4, Vg + (size_t)row * HDIM + c);
    }
    cp_commit();

    // stage Q once: scale by 0.125*log2e, round to tf32
    {
        int r = tid >> 4, c = (tid & 15) << 2;   // r 0..15, c 0..60
#pragma unroll
        for (int i = 0; i < 16; i++) {
            int row = r + i * 16;
            float4 v = *(const float4*)(Qg + (size_t)row * HDIM + c);
            *(float4*)(Qs + row * APAD + c) =
                make_float4(tf32_rna(v.x * QSC), tf32_rna(v.y * QSC),
                            tf32_rna(v.z * QSC), tf32_rna(v.w * QSC));
        }
    }

    float m_i[2][2], l_i[2][2];
    float o[2][8][4];
#pragma unroll
    for (int mt = 0; mt < 2; mt++) {
#pragma unroll
        for (int half = 0; half < 2; half++) { m_i[mt][half] = -3.0e38f; l_i[mt][half] = 0.0f; }
#pragma unroll
        for (int nt = 0; nt < 8; nt++)
#pragma unroll
            for (int j = 0; j < 4; j++) o[mt][nt][j] = 0.0f;
    }

    const int NB = SEQ / 64;
    for (int kb = 0; kb < NB; kb++) {
        cp_wait0();
        __syncthreads();   // buf[kb&1] staged; reads of buf[(kb+1)&1] (iter kb-1) done
        const uint32_t* uK = (const uint32_t*)(Ks + (kb & 1) * AKV);
        const uint32_t* uV = (const uint32_t*)(Vs + (kb & 1) * AKV);

        if (kb + 1 < NB) {   // issue next K/V block async into the other buffer
            const float* Kn = Kg + (size_t)(kb + 1) * 64 * HDIM;
            const float* Vn = Vg + (size_t)(kb + 1) * 64 * HDIM;
            uint32_t bo = (uint32_t)(((kb + 1) & 1) * AKV) * 4;
#pragma unroll
            for (int t = 0; t < 4; t++) {
                int slot = tid + t * 256;
                int row = slot >> 4, c = (slot & 15) << 2;
                cp16(sK0 + bo + (uint32_t)(row * APAD + c) * 4, Kn + (size_t)row * HDIM + c);
                cp16(sV0 + bo + (uint32_t)(row * APAD + c) * 4, Vn + (size_t)row * HDIM + c);
            }
            cp_commit();
        }

        // ---- S = Q K^T (32 rows x 64 keys per warp, log2-scaled) ----
        float s[2][8][4];
#pragma unroll
        for (int mt = 0; mt < 2; mt++)
#pragma unroll
            for (int nt = 0; nt < 8; nt++)
#pragma unroll
                for (int j = 0; j < 4; j++) s[mt][nt][j] = 0.0f;

#pragma unroll
        for (int ks = 0; ks < 8; ks++) {
            const int k0 = ks * 8;
            uint32_t qa[2][4];
#pragma unroll
            for (int mt = 0; mt < 2; mt++) {
                int base = (wq + mt * 16 + g) * APAD + k0 + tig;
                qa[mt][0] = uQ[base];
                qa[mt][1] = uQ[base + 8 * APAD];
                qa[mt][2] = uQ[base + 4];
                qa[mt][3] = uQ[base + 8 * APAD + 4];
            }
#pragma unroll
            for (int nt = 0; nt < 8; nt++) {
                int bb = (nt * 8 + g) * APAD + k0 + tig;
                uint32_t kf[2] = {uK[bb], uK[bb + 4]};
                mma8(s[0][nt], qa[0], kf);
                mma8(s[1][nt], qa[1], kf);
            }
        }

        // ---- online softmax (log2 domain) ----
#pragma unroll
        for (int mt = 0; mt < 2; mt++) {
#pragma unroll
            for (int half = 0; half < 2; half++) {
                float rmax = -3.0e38f;
#pragma unroll
                for (int nt = 0; nt < 8; nt++)
                    rmax = fmaxf(rmax, fmaxf(s[mt][nt][half * 2], s[mt][nt][half * 2 + 1]));
                rmax = fmaxf(rmax, __shfl_xor_sync(0xffffffffu, rmax, 1));
                rmax = fmaxf(rmax, __shfl_xor_sync(0xffffffffu, rmax, 2));
                float mnew  = fmaxf(m_i[mt][half], rmax);
                float alpha = ex2(m_i[mt][half] - mnew);
                m_i[mt][half] = mnew;
                float rs = 0.0f;
                int prow = (wq + mt * 16 + g + half * 8) * APAD + 2 * tig;
#pragma unroll
                for (int nt = 0; nt < 8; nt++) {
                    float p0 = ex2(s[mt][nt][half * 2] - mnew);
                    float p1 = ex2(s[mt][nt][half * 2 + 1] - mnew);
                    rs += p0 + p1;
                    *(float2*)(Ps + prow + nt * 8) = make_float2(tf32_rna(p0), tf32_rna(p1));
                    o[mt][nt][half * 2]     *= alpha;
                    o[mt][nt][half * 2 + 1] *= alpha;
                }
                rs += __shfl_xor_sync(0xffffffffu, rs, 1);
                rs += __shfl_xor_sync(0xffffffffu, rs, 2);
                l_i[mt][half] = l_i[mt][half] * alpha + rs;
            }
        }
        __syncwarp();   // Ps rows are warp-private; make stores visible

        // ---- O += P V ----
#pragma unroll
        for (int ks = 0; ks < 8; ks++) {
            const int k0 = ks * 8;
            uint32_t pa[2][4];
#pragma unroll
            for (int mt = 0; mt < 2; mt++) {
                int base = (wq + mt * 16 + g) * APAD + k0 + tig;
                pa[mt][0] = uP[base];
                pa[mt][1] = uP[base + 8 * APAD];
                pa[mt][2] = uP[base + 4];
                pa[mt][3] = uP[base + 8 * APAD + 4];
            }
#pragma unroll
            for (int nt = 0; nt < 8; nt++) {
                uint32_t vf[2] = {uV[(k0 + tig) * APAD + nt * 8 + g],
                                  uV[(k0 + tig + 4) * APAD + nt * 8 + g]};
                mma8(o[0][nt], pa[0], vf);
                mma8(o[1][nt], pa[1], vf);
            }
        }
    }

    // ---- epilogue: normalize, round to tf32 (gemm2 reads raw), write -------
    float* ob = g_att + ((size_t)b * SEQ + (size_t)qb * 256) * HIDDEN + h * HDIM;
#pragma unroll
    for (int mt = 0; mt < 2; mt++) {
#pragma unroll
        for (int half = 0; half < 2; half++) {
            float inv = 1.0f / l_i[mt][half];
            int row = wq + mt * 16 + g + half * 8;
#pragma unroll
            for (int nt = 0; nt < 8; nt++)
                *(float2*)(ob + (size_t)row * HIDDEN + nt * 8 + 2 * tig) =
                    make_float2(tf32_rna(o[mt][nt][half * 2] * inv),
                                tf32_rna(o[mt][nt][half * 2 + 1] * inv));
        }
    }
}

// ---------------- launch ---------------------------------------------------
extern "C" void kernel_launch(void* const* d_in, const int* in_sizes, int n_in,
                              void* d_out, int out_size)
{
    const float* x     = (const float*)d_in[0];
    const float* qkv_w = (const float*)d_in[1];
    const float* qkv_b = (const float*)d_in[2];
    const float* o_w   = (const float*)d_in[3];
    const float* o_b   = (const float*)d_in[4];
    float* out = (float*)d_out;

    cudaFuncSetAttribute(gemm_tf32<1>, cudaFuncAttributeMaxDynamicSharedMemorySize, GEMM_SMEM);
    cudaFuncSetAttribute(gemm_tf32<2>, cudaFuncAttributeMaxDynamicSharedMemorySize, GEMM_SMEM);
    cudaFuncSetAttribute(attn_tf32,   cudaFuncAttributeMaxDynamicSharedMemorySize, ATTN_SMEM);

    // 0) round inputs to tf32 once
    round_pre<<<592, 256>>>(x, qkv_w, o_w);
    // 1) QKV projection (1xTF32, cp.async, 64x64 warp tiles) + scatter
    gemm_tf32<1><<<dim3(3 * HIDDEN / 128, MROWS / 128), dim3(128), GEMM_SMEM>>>(
        qkv_b, nullptr, 3 * HIDDEN, HIDDEN);
    // 2) attention (1xTF32, 256-row q-blocks, 32 q-rows/warp, cp.async K/V)
    attn_tf32<<<dim3(SEQ / 256, HEADS, BATCH), dim3(256), ATTN_SMEM>>>();
    // 3) output projection (1xTF32, cp.async, 64x64 warp tiles)
    gemm_tf32<2><<<dim3(HIDDEN / 128, MROWS / 128), dim3(256 / 2), GEMM_SMEM>>>(
        o_b, out, HIDDEN, HIDDEN);
}